// round 16
// baseline (speedup 1.0000x reference)
#include <cuda_runtime.h>
#include <cuda_fp16.h>
#include <cstdint>

#define NL    8
#define NPOS  1024
#define DM    768
#define FT    4096
#define NPAIR 36
#define NT    256           // 8 warps: 2(M) x 4(N) grid of 64x32 warp tiles

// ---------------------------------------------------------------------------
// Static device scratch
// ---------------------------------------------------------------------------
__device__ __half g_xr  [(size_t)NL * NPOS * DM];       // 12.5 MB
__device__ __half g_wer [(size_t)NL * FT * DM];         //  50 MB
__device__ __half g_wdT [(size_t)NPAIR * DM * FT];      // 226 MB  [p][d][f]
__device__ __half g_feats[(size_t)NL * NPOS * FT];      //  67 MB
__device__ float  g_part[(size_t)NPAIR * NPOS * DM];    // 113 MB  fp32 partials
__device__ int    g_enc_done[NL];                       // encode layer counters
__device__ int    g_wdec_done[NPAIR];                   // wdec_T pair counters
__device__ int    g_pair_done[NPAIR];                   // decode pair counters

// ---------------------------------------------------------------------------
// Helpers
// ---------------------------------------------------------------------------
__device__ __forceinline__ uint32_t smem_u32(const void* p) {
    uint32_t a;
    asm("{ .reg .u64 t; cvta.to.shared.u64 t, %1; cvt.u32.u64 %0, t; }" : "=r"(a) : "l"(p));
    return a;
}
#define CP_ASYNC16(dst, src) \
    asm volatile("cp.async.cg.shared.global [%0], [%1], 16;" :: "r"(dst), "l"(src))
#define CP_COMMIT() asm volatile("cp.async.commit_group;" ::: "memory")
#define CP_WAIT1()  asm volatile("cp.async.wait_group 1;" ::: "memory")
#define CP_WAIT0()  asm volatile("cp.async.wait_group 0;" ::: "memory")

__device__ __forceinline__ void mma_f16(float c[4],
                                        unsigned a0, unsigned a1, unsigned a2, unsigned a3,
                                        unsigned b0, unsigned b1) {
    asm volatile(
        "mma.sync.aligned.m16n8k16.row.col.f32.f16.f16.f32 "
        "{%0,%1,%2,%3}, {%4,%5,%6,%7}, {%8,%9}, {%0,%1,%2,%3};"
        : "+f"(c[0]), "+f"(c[1]), "+f"(c[2]), "+f"(c[3])
        : "r"(a0), "r"(a1), "r"(a2), "r"(a3), "r"(b0), "r"(b1));
}
__device__ __forceinline__ void ldsm4(unsigned r[4], uint32_t addr) {
    asm volatile("ldmatrix.sync.aligned.m8n8.x4.shared.b16 {%0,%1,%2,%3}, [%4];"
        : "=r"(r[0]), "=r"(r[1]), "=r"(r[2]), "=r"(r[3]) : "r"(addr));
}
__device__ __forceinline__ void wait_ctr(int* ctr, int target) {
    int v;
    do {
        asm volatile("ld.global.acquire.gpu.b32 %0, [%1];" : "=r"(v) : "l"(ctr));
        if (v < target) __nanosleep(128);
    } while (v < target);
}

// ---------------------------------------------------------------------------
// SMEM: 3 stages, K-chunk 64 halves. A/B tiles 128 x 64 halves, stride 72.
// ---------------------------------------------------------------------------
#define STAGES 3
#define KC    64
#define HSTR  72
#define ROWB  (HSTR * 2)                  // 144 bytes per row
#define A_BYTES (128 * ROWB)              // 18432
#define B_OFF   A_BYTES
#define B_BYTES (128 * ROWB)              // 18432
#define STAGE   (A_BYTES + B_BYTES)       // 36864
#define SMEM_BYTES (STAGES * STAGE)       // 110592 per CTA (x2 CTAs = 221184)

__device__ __forceinline__ void load_tile(const __half* __restrict__ src, size_t gstr,
                                          uint32_t dst, int tid) {
#pragma unroll
    for (int q = 0; q < 4; q++) {
        int idx = tid + q * NT;
        int row = idx >> 3, seg = idx & 7;
        CP_ASYNC16(dst + row * ROWB + seg * 16, src + (size_t)row * gstr + seg * 8);
    }
}

__device__ __forceinline__ void compute_chunk(uint32_t sA, uint32_t sB,
                                              uint32_t a_off, uint32_t b_off,
                                              float acc[4][4][4]) {
#pragma unroll
    for (int kk = 0; kk < 4; kk++) {
        unsigned a[4][4], b[2][4];
#pragma unroll
        for (int mf = 0; mf < 4; mf++)
            ldsm4(a[mf], sA + mf * (16 * ROWB) + a_off + kk * 32);
#pragma unroll
        for (int p = 0; p < 2; p++)
            ldsm4(b[p], sB + p * (16 * ROWB) + b_off + kk * 32);
#pragma unroll
        for (int mf = 0; mf < 4; mf++)
#pragma unroll
            for (int p = 0; p < 2; p++) {
                mma_f16(acc[mf][2 * p],     a[mf][0], a[mf][1], a[mf][2], a[mf][3],
                        b[p][0], b[p][1]);
                mma_f16(acc[mf][2 * p + 1], a[mf][0], a[mf][1], a[mf][2], a[mf][3],
                        b[p][2], b[p][3]);
            }
    }
}

// shared GEMM mainloop (128x128 tile, 3-stage cp.async)
__device__ __forceinline__ void gemm_128(const __half* abase, size_t astr,
                                         const __half* bbase, size_t bstr, int NC,
                                         uint32_t sb, uint32_t a_off, uint32_t b_off,
                                         int tid, float acc[4][4][4]) {
    load_tile(abase, astr, sb, tid);
    load_tile(bbase, bstr, sb + B_OFF, tid);
    CP_COMMIT();
    load_tile(abase + KC, astr, sb + STAGE, tid);
    load_tile(bbase + KC, bstr, sb + STAGE + B_OFF, tid);
    CP_COMMIT();
    for (int c = 0; c < NC; c++) {
        if (c + 1 < NC) { CP_WAIT1(); } else { CP_WAIT0(); }
        __syncthreads();
        int nc = c + 2;
        if (nc < NC) {
            uint32_t s = sb + (nc % STAGES) * STAGE;
            load_tile(abase + nc * KC, astr, s, tid);
            load_tile(bbase + nc * KC, bstr, s + B_OFF, tid);
            CP_COMMIT();
        }
        uint32_t st = sb + (c % STAGES) * STAGE;
        compute_chunk(st, st + B_OFF, a_off, b_off, acc);
    }
}

// ---------------------------------------------------------------------------
// Prep kernels
// ---------------------------------------------------------------------------
__global__ void zero_ctrs() {
    int t = threadIdx.x;
    if (t < NL) g_enc_done[t] = 0;
    if (t < NPAIR) { g_wdec_done[t] = 0; g_pair_done[t] = 0; }
}
__global__ void half_copy(const float* __restrict__ src, __half* __restrict__ dst) {
    size_t i = ((size_t)blockIdx.x * 256 + threadIdx.x) * 8;
    float4 v0 = *(const float4*)(src + i);
    float4 v1 = *(const float4*)(src + i + 4);
    __half2 h[4] = { __floats2half2_rn(v0.x, v0.y), __floats2half2_rn(v0.z, v0.w),
                     __floats2half2_rn(v1.x, v1.y), __floats2half2_rn(v1.z, v1.w) };
    *(uint4*)(dst + i) = *(uint4*)h;
}
// W_dec[i,j][f][d] -> g_wdT[p][d][f], half; signals g_wdec_done[p]
#define WDEC_BLOCKS_PER_PAIR ((FT / 32) * (DM / 32))   // 3072
__global__ void wdec_T(const float* __restrict__ W_dec) {
    int p = blockIdx.z;
    int j = 0, a = 0;
    while (a + j + 1 <= p) { a += j + 1; ++j; }
    int i = p - a;
    int f0 = blockIdx.x * 32, d0 = blockIdx.y * 32;
    int tx = threadIdx.x, ty = threadIdx.y;
    __shared__ float t[32][33];
    const float* src = W_dec + (size_t)(i * NL + j) * FT * DM;
#pragma unroll
    for (int r = 0; r < 4; r++)
        t[ty + r * 8][tx] = src[(size_t)(f0 + ty + r * 8) * DM + d0 + tx];
    __syncthreads();
    __half* dst = g_wdT + (size_t)p * DM * FT;
#pragma unroll
    for (int r = 0; r < 4; r++)
        dst[(size_t)(d0 + ty + r * 8) * FT + f0 + tx] = __float2half_rn(t[tx][ty + r * 8]);
    __threadfence();
    __syncthreads();
    if (tx == 0 && ty == 0) atomicAdd(&g_wdec_done[p], 1);
}

// ---------------------------------------------------------------------------
// Fully fused encode + decode + reduce.
// Grid: [0, 2048)        encode, layer-major (layer = bid/256)
//       [2048, 3776)     decode, i-major ordering, gated on enc+wdec counters
//       [3776, 9920)     reduce, gated on pair counters
// ---------------------------------------------------------------------------
#define ENC_PER_L (32 * 8)                     // 256 CTAs per layer
#define ENC_CTAS  (NL * ENC_PER_L)             // 2048
#define TILES_PER_PAIR 48                      // 8 mtiles(128) x 6 ntiles(128)
#define DEC_CTAS  (NPAIR * TILES_PER_PAIR)     // 1728
#define RED_PER_J (NPOS * DM / 1024)           // 768
#define RED_CTAS  (NL * RED_PER_J)             // 6144

__global__ __launch_bounds__(NT, 2)
void fused_all(const float* __restrict__ b_enc,
               const float* __restrict__ b_dec, float* __restrict__ out) {
    extern __shared__ float smem[];
    const int bid = blockIdx.x;
    const int tid = threadIdx.x;
    const int lane = tid & 31, warp = tid >> 5;
    const int wm = warp & 1, wn = warp >> 1;
    const uint32_t sb = smem_u32(smem);
    const uint32_t a_off = (wm * 64 + (lane & 15)) * ROWB + (lane >> 4) * 16;
    const uint32_t b_off = (wn * 32 + (lane & 7) + ((lane >> 4) << 3)) * ROWB
                         + ((lane >> 3) & 1) * 16;

    if (bid < ENC_CTAS) {
        // ---------------- encode ----------------
        const int l = bid / ENC_PER_L, sub = bid % ENC_PER_L;
        const int n0 = (sub % 32) * 128, m0 = (sub / 32) * 128;

        float acc[4][4][4];
#pragma unroll
        for (int a = 0; a < 4; a++)
#pragma unroll
            for (int b = 0; b < 4; b++)
#pragma unroll
                for (int c = 0; c < 4; c++) acc[a][b][c] = 0.f;

        gemm_128(g_xr + ((size_t)l * NPOS + m0) * DM, DM,
                 g_wer + ((size_t)l * FT + n0) * DM, DM, DM / KC,
                 sb, a_off, b_off, tid, acc);

        const float* be = b_enc + (size_t)l * FT + n0;
#pragma unroll
        for (int mf = 0; mf < 4; mf++) {
            int r0 = m0 + wm * 64 + mf * 16 + (lane >> 2);
            __half* d0 = g_feats + ((size_t)l * NPOS + r0) * FT + n0;
            __half* d1 = d0 + 8 * FT;
#pragma unroll
            for (int nf = 0; nf < 4; nf++) {
                int c0 = wn * 32 + nf * 8 + (lane & 3) * 2;
                float b0 = be[c0], b1 = be[c0 + 1];
                __half2 v0 = __floats2half2_rn(fmaxf(acc[mf][nf][0] + b0, 0.f),
                                               fmaxf(acc[mf][nf][1] + b1, 0.f));
                __half2 v1 = __floats2half2_rn(fmaxf(acc[mf][nf][2] + b0, 0.f),
                                               fmaxf(acc[mf][nf][3] + b1, 0.f));
                *(__half2*)(d0 + c0) = v0;
                *(__half2*)(d1 + c0) = v1;
            }
        }
        __threadfence();
        __syncthreads();
        if (tid == 0) atomicAdd(&g_enc_done[l], 1);
    } else if (bid < ENC_CTAS + DEC_CTAS) {
        // ---------------- decode (i-major order) ----------------
        const int q = bid - ENC_CTAS;
        const int pi = q / TILES_PER_PAIR, sub = q % TILES_PER_PAIR;
        int i = 0, rem = pi;
        while (rem >= NL - i) { rem -= NL - i; ++i; }
        const int j = i + rem;
        const int p = j * (j + 1) / 2 + i;
        const int m0 = (sub / 6) * 128, n0 = (sub % 6) * 128;

        if (tid == 0) {
            wait_ctr(&g_enc_done[i], ENC_PER_L);
            wait_ctr(&g_wdec_done[p], WDEC_BLOCKS_PER_PAIR);
        }
        __syncthreads();

        float acc[4][4][4];
#pragma unroll
        for (int a = 0; a < 4; a++)
#pragma unroll
            for (int b = 0; b < 4; b++)
#pragma unroll
                for (int c = 0; c < 4; c++) acc[a][b][c] = 0.f;

        gemm_128(g_feats + ((size_t)i * NPOS + m0) * FT, FT,
                 g_wdT + (size_t)p * DM * FT + (size_t)n0 * FT, FT, FT / KC,
                 sb, a_off, b_off, tid, acc);

#pragma unroll
        for (int mf = 0; mf < 4; mf++) {
            int r0 = m0 + wm * 64 + mf * 16 + (lane >> 2);
            float* d0 = g_part + ((size_t)p * NPOS + r0) * DM + n0;
            float* d1 = d0 + 8 * DM;
#pragma unroll
            for (int nf = 0; nf < 4; nf++) {
                int c0 = wn * 32 + nf * 8 + (lane & 3) * 2;
                float2 v0 = { acc[mf][nf][0], acc[mf][nf][1] };
                float2 v1 = { acc[mf][nf][2], acc[mf][nf][3] };
                *(float2*)(d0 + c0) = v0;
                *(float2*)(d1 + c0) = v1;
            }
        }
        __threadfence();
        __syncthreads();
        if (tid == 0) atomicAdd(&g_pair_done[p], 1);
    } else {
        // ---------------- reduce ----------------
        const int r = bid - ENC_CTAS - DEC_CTAS;
        const int jj = r / RED_PER_J;
        const int blk = r % RED_PER_J;
        const int base = jj * (jj + 1) / 2;

        if (tid == 0)
            for (int i = 0; i <= jj; i++)
                wait_ctr(&g_pair_done[base + i], TILES_PER_PAIR);
        __syncthreads();

        size_t lin = ((size_t)blk * 256 + tid) * 4;
        int d = (int)(lin % DM);
        float4 acc = *(const float4*)(b_dec + (size_t)jj * DM + d);
        for (int i = 0; i <= jj; i++) {
            float4 v = *(const float4*)(g_part + (size_t)(base + i) * NPOS * DM + lin);
            acc.x += v.x; acc.y += v.y; acc.z += v.z; acc.w += v.w;
        }
        *(float4*)(out + (size_t)jj * NPOS * DM + lin) = acc;
    }
}

// ---------------------------------------------------------------------------
extern "C" void kernel_launch(void* const* d_in, const int* in_sizes, int n_in,
                              void* d_out, int out_size) {
    const float* x     = (const float*)d_in[0];
    const float* W_enc = (const float*)d_in[1];
    const float* b_enc = (const float*)d_in[2];
    const float* W_dec = (const float*)d_in[3];
    const float* b_dec = (const float*)d_in[4];
    float* out = (float*)d_out;

    static cudaStream_t s2 = nullptr;
    static cudaEvent_t evA = nullptr, evB = nullptr;
    if (!s2) {
        cudaFuncSetAttribute(fused_all, cudaFuncAttributeMaxDynamicSharedMemorySize, SMEM_BYTES);
        cudaStreamCreateWithFlags(&s2, cudaStreamNonBlocking);
        cudaEventCreateWithFlags(&evA, cudaEventDisableTiming);
        cudaEventCreateWithFlags(&evB, cudaEventDisableTiming);
    }

    __half* g_xr_p;   cudaGetSymbolAddress((void**)&g_xr_p,  g_xr);
    __half* g_wer_p;  cudaGetSymbolAddress((void**)&g_wer_p, g_wer);

    // Zero counters first (ordered before both streams' work).
    zero_ctrs<<<1, 64>>>();
    cudaEventRecord(evA, 0);
    cudaStreamWaitEvent(s2, evA, 0);

    // Side stream: W_dec transpose+convert (signals g_wdec_done per pair).
    wdec_T<<<dim3(FT / 32, DM / 32, NPAIR), dim3(32, 8), 0, s2>>>(W_dec);
    cudaEventRecord(evB, s2);

    // Main stream: input prep, then the fully fused mega-kernel.
    half_copy<<<(NL * NPOS * DM) / 2048, 256>>>(x, g_xr_p);
    half_copy<<<(NL * FT * DM) / 2048, 256>>>(W_enc, g_wer_p);
    fused_all<<<ENC_CTAS + DEC_CTAS + RED_CTAS, NT, SMEM_BYTES>>>(b_enc, b_dec, out);

    // Keep graph dependency on the side stream (ensures wdec_T is in the graph).
    cudaStreamWaitEvent(0, evB, 0);
}

// round 17
// speedup vs baseline: 1.0620x; 1.0620x over previous
#include <cuda_runtime.h>
#include <cuda_fp16.h>
#include <cstdint>

#define NL    8
#define NPOS  1024
#define DM    768
#define FT    4096
#define NPAIR 36
#define NT    256           // 8 warps: 2(M) x 4(N) grid of 64x32 warp tiles

// ---------------------------------------------------------------------------
// Static device scratch
// ---------------------------------------------------------------------------
__device__ __half g_xr  [(size_t)NL * NPOS * DM];       // 12.5 MB
__device__ __half g_wer [(size_t)NL * FT * DM];         //  50 MB
__device__ __half g_wdT [(size_t)NPAIR * DM * FT];      // 226 MB  [p][d][f]
__device__ __half g_feats[(size_t)NL * NPOS * FT];      //  67 MB
__device__ float  g_part[(size_t)NPAIR * NPOS * DM];    // 113 MB  fp32 partials
__device__ int    g_pair_done[NPAIR];                   // decode->reduce gating

// ---------------------------------------------------------------------------
// Helpers
// ---------------------------------------------------------------------------
__device__ __forceinline__ uint32_t smem_u32(const void* p) {
    uint32_t a;
    asm("{ .reg .u64 t; cvta.to.shared.u64 t, %1; cvt.u32.u64 %0, t; }" : "=r"(a) : "l"(p));
    return a;
}
#define CP_ASYNC16(dst, src) \
    asm volatile("cp.async.cg.shared.global [%0], [%1], 16;" :: "r"(dst), "l"(src))
#define CP_COMMIT() asm volatile("cp.async.commit_group;" ::: "memory")
#define CP_WAIT1()  asm volatile("cp.async.wait_group 1;" ::: "memory")
#define CP_WAIT0()  asm volatile("cp.async.wait_group 0;" ::: "memory")

__device__ __forceinline__ void mma_f16(float c[4],
                                        unsigned a0, unsigned a1, unsigned a2, unsigned a3,
                                        unsigned b0, unsigned b1) {
    asm volatile(
        "mma.sync.aligned.m16n8k16.row.col.f32.f16.f16.f32 "
        "{%0,%1,%2,%3}, {%4,%5,%6,%7}, {%8,%9}, {%0,%1,%2,%3};"
        : "+f"(c[0]), "+f"(c[1]), "+f"(c[2]), "+f"(c[3])
        : "r"(a0), "r"(a1), "r"(a2), "r"(a3), "r"(b0), "r"(b1));
}
__device__ __forceinline__ void ldsm4(unsigned r[4], uint32_t addr) {
    asm volatile("ldmatrix.sync.aligned.m8n8.x4.shared.b16 {%0,%1,%2,%3}, [%4];"
        : "=r"(r[0]), "=r"(r[1]), "=r"(r[2]), "=r"(r[3]) : "r"(addr));
}
__device__ __forceinline__ void wait_ctr(int* ctr, int target) {
    int v;
    do {
        asm volatile("ld.global.acquire.gpu.b32 %0, [%1];" : "=r"(v) : "l"(ctr));
        if (v < target) __nanosleep(128);
    } while (v < target);
}

// ---------------------------------------------------------------------------
// SMEM: 3 stages, K-chunk 64 halves. A/B tiles 128 x 64 halves, stride 72.
// ---------------------------------------------------------------------------
#define STAGES 3
#define KC    64
#define HSTR  72
#define ROWB  (HSTR * 2)                  // 144 bytes per row
#define A_BYTES (128 * ROWB)              // 18432
#define B_OFF   A_BYTES
#define B_BYTES (128 * ROWB)              // 18432
#define STAGE   (A_BYTES + B_BYTES)       // 36864
#define SMEM_BYTES (STAGES * STAGE)       // 110592 per CTA (x2 CTAs = 221184)

__device__ __forceinline__ void load_tile(const __half* __restrict__ src, size_t gstr,
                                          uint32_t dst, int tid) {
#pragma unroll
    for (int q = 0; q < 4; q++) {
        int idx = tid + q * NT;
        int row = idx >> 3, seg = idx & 7;
        CP_ASYNC16(dst + row * ROWB + seg * 16, src + (size_t)row * gstr + seg * 8);
    }
}

__device__ __forceinline__ void compute_chunk(uint32_t sA, uint32_t sB,
                                              uint32_t a_off, uint32_t b_off,
                                              float acc[4][4][4]) {
#pragma unroll
    for (int kk = 0; kk < 4; kk++) {
        unsigned a[4][4], b[2][4];
#pragma unroll
        for (int mf = 0; mf < 4; mf++)
            ldsm4(a[mf], sA + mf * (16 * ROWB) + a_off + kk * 32);
#pragma unroll
        for (int p = 0; p < 2; p++)
            ldsm4(b[p], sB + p * (16 * ROWB) + b_off + kk * 32);
#pragma unroll
        for (int mf = 0; mf < 4; mf++)
#pragma unroll
            for (int p = 0; p < 2; p++) {
                mma_f16(acc[mf][2 * p],     a[mf][0], a[mf][1], a[mf][2], a[mf][3],
                        b[p][0], b[p][1]);
                mma_f16(acc[mf][2 * p + 1], a[mf][0], a[mf][1], a[mf][2], a[mf][3],
                        b[p][2], b[p][3]);
            }
    }
}

// ---------------------------------------------------------------------------
// Prep: single fused fp32->half copy for x then W_enc; zeroes counters.
// ---------------------------------------------------------------------------
#define X_VECS  ((size_t)NL * NPOS * DM / 8)     // 786432
#define WE_VECS ((size_t)NL * FT * DM / 8)       // 3145728
__global__ void prep_inputs(const float* __restrict__ x,
                            const float* __restrict__ W_enc) {
    if (blockIdx.x == 0 && threadIdx.x < NPAIR) g_pair_done[threadIdx.x] = 0;
    size_t v = (size_t)blockIdx.x * 256 + threadIdx.x;
    const float* src;
    __half* dst;
    if (v < X_VECS) {
        src = x + v * 8;
        dst = g_xr + v * 8;
    } else {
        size_t w = v - X_VECS;
        src = W_enc + w * 8;
        dst = g_wer + w * 8;
    }
    float4 v0 = *(const float4*)(src);
    float4 v1 = *(const float4*)(src + 4);
    __half2 h[4] = { __floats2half2_rn(v0.x, v0.y), __floats2half2_rn(v0.z, v0.w),
                     __floats2half2_rn(v1.x, v1.y), __floats2half2_rn(v1.z, v1.w) };
    *(uint4*)dst = *(uint4*)h;
}

// W_dec[i,j][f][d] -> g_wdT[p][d][f], half
__global__ void wdec_T(const float* __restrict__ W_dec) {
    int p = blockIdx.z;
    int j = 0, a = 0;
    while (a + j + 1 <= p) { a += j + 1; ++j; }
    int i = p - a;
    int f0 = blockIdx.x * 32, d0 = blockIdx.y * 32;
    int tx = threadIdx.x, ty = threadIdx.y;
    __shared__ float t[32][33];
    const float* src = W_dec + (size_t)(i * NL + j) * FT * DM;
#pragma unroll
    for (int r = 0; r < 4; r++)
        t[ty + r * 8][tx] = src[(size_t)(f0 + ty + r * 8) * DM + d0 + tx];
    __syncthreads();
    __half* dst = g_wdT + (size_t)p * DM * FT;
#pragma unroll
    for (int r = 0; r < 4; r++)
        dst[(size_t)(d0 + ty + r * 8) * FT + f0 + tx] = __float2half_rn(t[tx][ty + r * 8]);
}

// ---------------------------------------------------------------------------
// Encoder. grid (FT/128, NPOS/128, NL)
// ---------------------------------------------------------------------------
__global__ __launch_bounds__(NT, 2)
void encode_tc(const float* __restrict__ b_enc) {
    extern __shared__ float smem[];
    const int l = blockIdx.z, m0 = blockIdx.y * 128, n0 = blockIdx.x * 128;
    const int tid = threadIdx.x, lane = tid & 31, warp = tid >> 5;
    const int wm = warp & 1, wn = warp >> 1;
    const uint32_t sb = smem_u32(smem);

    const uint32_t a_off = (wm * 64 + (lane & 15)) * ROWB + (lane >> 4) * 16;
    const uint32_t b_off = (wn * 32 + (lane & 7) + ((lane >> 4) << 3)) * ROWB
                         + ((lane >> 3) & 1) * 16;

    float acc[4][4][4];
#pragma unroll
    for (int a = 0; a < 4; a++)
#pragma unroll
        for (int b = 0; b < 4; b++)
#pragma unroll
            for (int c = 0; c < 4; c++) acc[a][b][c] = 0.f;

    const __half* abase = g_xr  + ((size_t)l * NPOS + m0) * DM;
    const __half* bbase = g_wer + ((size_t)l * FT + n0) * DM;
    const int NC = DM / KC;

    load_tile(abase, DM, sb, tid);
    load_tile(bbase, DM, sb + B_OFF, tid);
    CP_COMMIT();
    load_tile(abase + KC, DM, sb + STAGE, tid);
    load_tile(bbase + KC, DM, sb + STAGE + B_OFF, tid);
    CP_COMMIT();

    for (int c = 0; c < NC; c++) {
        if (c + 1 < NC) { CP_WAIT1(); } else { CP_WAIT0(); }
        __syncthreads();
        int nc = c + 2;
        if (nc < NC) {
            uint32_t s = sb + (nc % STAGES) * STAGE;
            load_tile(abase + nc * KC, DM, s, tid);
            load_tile(bbase + nc * KC, DM, s + B_OFF, tid);
            CP_COMMIT();
        }
        uint32_t st = sb + (c % STAGES) * STAGE;
        compute_chunk(st, st + B_OFF, a_off, b_off, acc);
    }

    const float* be = b_enc + (size_t)l * FT + n0;
#pragma unroll
    for (int mf = 0; mf < 4; mf++) {
        int r0 = m0 + wm * 64 + mf * 16 + (lane >> 2);
        __half* d0 = g_feats + ((size_t)l * NPOS + r0) * FT + n0;
        __half* d1 = d0 + 8 * FT;
#pragma unroll
        for (int nf = 0; nf < 4; nf++) {
            int c0 = wn * 32 + nf * 8 + (lane & 3) * 2;
            float b0 = be[c0], b1 = be[c0 + 1];
            __half2 v0 = __floats2half2_rn(fmaxf(acc[mf][nf][0] + b0, 0.f),
                                           fmaxf(acc[mf][nf][1] + b1, 0.f));
            __half2 v1 = __floats2half2_rn(fmaxf(acc[mf][nf][2] + b0, 0.f),
                                           fmaxf(acc[mf][nf][3] + b1, 0.f));
            *(__half2*)(d0 + c0) = v0;
            *(__half2*)(d1 + c0) = v1;
        }
    }
}

// ---------------------------------------------------------------------------
// Fused decode + reduce. 1728 decode CTAs (p-ascending => j-ascending) then
// 6144 reduce CTAs; reduce accumulates each pair incrementally as it lands.
// ---------------------------------------------------------------------------
#define DEC_CTAS (NPAIR * 48)                 // 1728
#define RED_PER_J (NPOS * DM / 1024)          // 768
#define RED_CTAS (NL * RED_PER_J)             // 6144

__global__ __launch_bounds__(NT, 2)
void decode_reduce(const float* __restrict__ b_dec, float* __restrict__ out) {
    extern __shared__ float smem[];
    const int bid = blockIdx.x;
    const int tid = threadIdx.x;

    if (bid < DEC_CTAS) {
        // ---------------- decode path ----------------
        const int p = bid / 48, sub = bid % 48;
        const int m0 = (sub / 6) * 128, n0 = (sub % 6) * 128;
        int j = 0, a0 = 0;
        while (a0 + j + 1 <= p) { a0 += j + 1; ++j; }
        const int i = p - a0;
        const int lane = tid & 31, warp = tid >> 5;
        const int wm = warp & 1, wn = warp >> 1;
        const uint32_t sb = smem_u32(smem);

        const uint32_t a_off = (wm * 64 + (lane & 15)) * ROWB + (lane >> 4) * 16;
        const uint32_t b_off = (wn * 32 + (lane & 7) + ((lane >> 4) << 3)) * ROWB
                             + ((lane >> 3) & 1) * 16;

        float acc[4][4][4];
#pragma unroll
        for (int a = 0; a < 4; a++)
#pragma unroll
            for (int b = 0; b < 4; b++)
#pragma unroll
                for (int c = 0; c < 4; c++) acc[a][b][c] = 0.f;

        const __half* abase = g_feats + ((size_t)i * NPOS + m0) * FT;
        const __half* bbase = g_wdT + (size_t)p * DM * FT + (size_t)n0 * FT;
        const int NC = FT / KC;

        load_tile(abase, FT, sb, tid);
        load_tile(bbase, FT, sb + B_OFF, tid);
        CP_COMMIT();
        load_tile(abase + KC, FT, sb + STAGE, tid);
        load_tile(bbase + KC, FT, sb + STAGE + B_OFF, tid);
        CP_COMMIT();

        for (int c = 0; c < NC; c++) {
            if (c + 1 < NC) { CP_WAIT1(); } else { CP_WAIT0(); }
            __syncthreads();
            int nc = c + 2;
            if (nc < NC) {
                uint32_t s = sb + (nc % STAGES) * STAGE;
                load_tile(abase + nc * KC, FT, s, tid);
                load_tile(bbase + nc * KC, FT, s + B_OFF, tid);
                CP_COMMIT();
            }
            uint32_t st = sb + (c % STAGES) * STAGE;
            compute_chunk(st, st + B_OFF, a_off, b_off, acc);
        }

#pragma unroll
        for (int mf = 0; mf < 4; mf++) {
            int r0 = m0 + wm * 64 + mf * 16 + (lane >> 2);
            float* d0 = g_part + ((size_t)p * NPOS + r0) * DM + n0;
            float* d1 = d0 + 8 * DM;
#pragma unroll
            for (int nf = 0; nf < 4; nf++) {
                int c0 = wn * 32 + nf * 8 + (lane & 3) * 2;
                float2 v0 = { acc[mf][nf][0], acc[mf][nf][1] };
                float2 v1 = { acc[mf][nf][2], acc[mf][nf][3] };
                *(float2*)(d0 + c0) = v0;
                *(float2*)(d1 + c0) = v1;
            }
        }
        __threadfence();
        __syncthreads();
        if (tid == 0) atomicAdd(&g_pair_done[p], 1);
    } else {
        // ---------------- reduce path (incremental) ----------------
        const int r = bid - DEC_CTAS;
        const int jj = r / RED_PER_J;
        const int blk = r % RED_PER_J;
        const int base = jj * (jj + 1) / 2;
        __shared__ int s_ready;

        size_t lin = ((size_t)blk * 256 + tid) * 4;
        int d = (int)(lin % DM);
        float4 acc = *(const float4*)(b_dec + (size_t)jj * DM + d);

        for (int i = 0; i <= jj; i++) {
            if (tid == 0) {
                wait_ctr(&g_pair_done[base + i], 48);
                s_ready = 1;
            }
            __syncthreads();
            float4 v = *(const float4*)(g_part + (size_t)(base + i) * NPOS * DM + lin);
            acc.x += v.x; acc.y += v.y; acc.z += v.z; acc.w += v.w;
            __syncthreads();
        }
        *(float4*)(out + (size_t)jj * NPOS * DM + lin) = acc;
    }
}

// ---------------------------------------------------------------------------
extern "C" void kernel_launch(void* const* d_in, const int* in_sizes, int n_in,
                              void* d_out, int out_size) {
    const float* x     = (const float*)d_in[0];
    const float* W_enc = (const float*)d_in[1];
    const float* b_enc = (const float*)d_in[2];
    const float* W_dec = (const float*)d_in[3];
    const float* b_dec = (const float*)d_in[4];
    float* out = (float*)d_out;

    static cudaStream_t s2 = nullptr;
    static cudaEvent_t evA = nullptr, evB = nullptr;
    if (!s2) {
        cudaFuncSetAttribute(encode_tc, cudaFuncAttributeMaxDynamicSharedMemorySize, SMEM_BYTES);
        cudaFuncSetAttribute(decode_reduce, cudaFuncAttributeMaxDynamicSharedMemorySize, SMEM_BYTES);
        cudaStreamCreateWithFlags(&s2, cudaStreamNonBlocking);
        cudaEventCreateWithFlags(&evA, cudaEventDisableTiming);
        cudaEventCreateWithFlags(&evB, cudaEventDisableTiming);
    }

    // Fork: W_dec transpose+convert on side stream, overlapped with encode chain.
    cudaEventRecord(evA, 0);
    cudaStreamWaitEvent(s2, evA, 0);
    wdec_T<<<dim3(FT / 32, DM / 32, NPAIR), dim3(32, 8), 0, s2>>>(W_dec);
    cudaEventRecord(evB, s2);

    prep_inputs<<<(unsigned)(X_VECS + WE_VECS) / 256, 256>>>(x, W_enc);
    encode_tc<<<dim3(FT / 128, NPOS / 128, NL), NT, SMEM_BYTES>>>(b_enc);

    // Join, then fused decode + reduce.
    cudaStreamWaitEvent(0, evB, 0);
    decode_reduce<<<DEC_CTAS + RED_CTAS, NT, SMEM_BYTES>>>(b_dec, out);
}